// round 15
// baseline (speedup 1.0000x reference)
#include <cuda_runtime.h>
#include <cuda_fp16.h>
#include <cstdint>

#define N_NODES 100000
#define N_EDGES 1600000
#define IN_C 128
#define HID_C 256
#define OUT_C 128
#define SCAN_NB ((N_NODES + 1023) / 1024)   // 98

// ================= scratch =================
__device__ __half  g_xh  [N_NODES * IN_C];       // fp16 copy of x
__device__ __half  g_agg1[N_NODES * IN_C];       // fp16 aggregated input (conv1)
__device__ __half  g_h   [N_NODES * HID_C];      // conv1 output (fp16, relu)
__device__ __half  g_agg2[N_NODES * HID_C];      // fp16 aggregated input (conv2)
__device__ __half  g_Wf1[IN_C * HID_C];          // fragment-packed fp16 weights
__device__ __half  g_Wf2[HID_C * HID_C];
__device__ __half  g_Wf3[HID_C * HID_C];
__device__ __half  g_Wf4[HID_C * OUT_C];
__device__ int     g_cnt[N_NODES];
__device__ int     g_rowoff[N_NODES + 1];
__device__ int     g_cursor[N_NODES];
__device__ int     g_csrsrc[N_EDGES];
__device__ int     g_bsum[SCAN_NB];

// ================= helpers =================
__device__ __forceinline__ uint32_t smem_u32(const void* p) {
    uint32_t a;
    asm("{ .reg .u64 t; cvta.to.shared.u64 t, %1; cvt.u32.u64 %0, t; }" : "=r"(a) : "l"(p));
    return a;
}
__device__ __forceinline__ void cp_async16(uint32_t dst, const void* src, bool pred) {
    int sz = pred ? 16 : 0;
    asm volatile("cp.async.ca.shared.global [%0], [%1], 16, %2;"
                 :: "r"(dst), "l"(src), "r"(sz) : "memory");
}
#define CP_COMMIT() asm volatile("cp.async.commit_group;" ::: "memory")
#define CP_WAIT(n)  asm volatile("cp.async.wait_group %0;" :: "n"(n) : "memory")

__device__ __forceinline__ void mma_f16(float* d, uint32_t a0, uint32_t a1,
                                        uint32_t a2, uint32_t a3,
                                        uint32_t b0, uint32_t b1) {
    asm volatile(
        "mma.sync.aligned.m16n8k16.row.col.f32.f16.f16.f32 "
        "{%0,%1,%2,%3}, {%4,%5,%6,%7}, {%8,%9}, {%0,%1,%2,%3};"
        : "+f"(d[0]), "+f"(d[1]), "+f"(d[2]), "+f"(d[3])
        : "r"(a0), "r"(a1), "r"(a2), "r"(a3), "r"(b0), "r"(b1));
}
__device__ __forceinline__ uint32_t pack_h2(float lo, float hi) {
    __half2 h = __floats2half2_rn(lo, hi);
    return *(uint32_t*)&h;
}
__device__ __forceinline__ void h8_add(float* acc, uint4 v) {
    float2 f;
    f = __half22float2(*(__half2*)&v.x); acc[0] += f.x; acc[1] += f.y;
    f = __half22float2(*(__half2*)&v.y); acc[2] += f.x; acc[3] += f.y;
    f = __half22float2(*(__half2*)&v.z); acc[4] += f.x; acc[5] += f.y;
    f = __half22float2(*(__half2*)&v.w); acc[6] += f.x; acc[7] += f.y;
}
__device__ __forceinline__ void h4_add(float* acc, uint2 v) {
    float2 f;
    f = __half22float2(*(__half2*)&v.x); acc[0] += f.x; acc[1] += f.y;
    f = __half22float2(*(__half2*)&v.y); acc[2] += f.x; acc[3] += f.y;
}

// ================= x -> fp16 convert =================
__global__ void convert_kernel(const float4* __restrict__ x, uint4* __restrict__ xh, int n8)
{
    int i = blockIdx.x * 256 + threadIdx.x;
    if (i >= n8) return;
    float4 a = x[2 * i], b = x[2 * i + 1];
    uint4 o;
    o.x = pack_h2(a.x, a.y);
    o.y = pack_h2(a.z, a.w);
    o.z = pack_h2(b.x, b.y);
    o.w = pack_h2(b.z, b.w);
    xh[i] = o;
}

// ================= weight fragment-pack (fp16) =================
template <int K, int NTOT>
__global__ void pack_kernel(const float* __restrict__ W, __half* __restrict__ Wf)
{
    constexpr int NT = NTOT / 64;
    constexpr int PER_G = 4 * NTOT;             // uint4s per 32-k chunk
    int id = blockIdx.x * 256 + threadIdx.x;
    if (id >= K * NTOT / 8) return;
    int q  = id % PER_G;
    int g  = id / PER_G;
    int lane = q & 31;
    int p    = (q >> 5) & 3;
    int rest = q >> 7;
    int wt   = rest % NT;
    int ks   = rest / NT;

    int gid = lane >> 2, tig = lane & 3;
    int n0 = wt * 64 + 2 * p * 8 + gid;
    int k0 = g * 32 + ks * 16 + tig * 2;

    uint4 v;
    v.x = pack_h2(W[(size_t)k0       * NTOT + n0],     W[(size_t)(k0 + 1) * NTOT + n0]);
    v.y = pack_h2(W[(size_t)(k0 + 8) * NTOT + n0],     W[(size_t)(k0 + 9) * NTOT + n0]);
    v.z = pack_h2(W[(size_t)k0       * NTOT + n0 + 8], W[(size_t)(k0 + 1) * NTOT + n0 + 8]);
    v.w = pack_h2(W[(size_t)(k0 + 8) * NTOT + n0 + 8], W[(size_t)(k0 + 9) * NTOT + n0 + 8]);
    *(uint4*)&Wf[(size_t)id * 8] = v;
}

// ================= CSR build =================
__global__ void hist_kernel(const int* __restrict__ dst, int* __restrict__ cnt)
{
    int e = blockIdx.x * 256 + threadIdx.x;
    if (e < N_EDGES) atomicAdd(&cnt[dst[e]], 1);
}

__global__ void scan1_kernel(const int* __restrict__ cnt, int* __restrict__ rowoff,
                             int* __restrict__ bsum)
{
    __shared__ int sh[1024];
    int tid = threadIdx.x;
    int i = blockIdx.x * 1024 + tid;
    int v = (i < N_NODES) ? cnt[i] : 0;
    sh[tid] = v;
    __syncthreads();
#pragma unroll
    for (int off = 1; off < 1024; off <<= 1) {
        int t = (tid >= off) ? sh[tid - off] : 0;
        __syncthreads();
        sh[tid] += t;
        __syncthreads();
    }
    if (i < N_NODES) rowoff[i] = sh[tid] - v;
    if (tid == 1023) bsum[blockIdx.x] = sh[tid];
}

__global__ void scan2_kernel(int* __restrict__ bsum)
{
    __shared__ int sh[128];
    int tid = threadIdx.x;
    int v = (tid < SCAN_NB) ? bsum[tid] : 0;
    sh[tid] = v;
    __syncthreads();
#pragma unroll
    for (int off = 1; off < 128; off <<= 1) {
        int t = (tid >= off) ? sh[tid - off] : 0;
        __syncthreads();
        sh[tid] += t;
        __syncthreads();
    }
    if (tid < SCAN_NB) bsum[tid] = sh[tid] - v;
}

__global__ void scan3_kernel(int* __restrict__ rowoff, const int* __restrict__ bsum,
                             int* __restrict__ cursor)
{
    int i = blockIdx.x * 1024 + threadIdx.x;
    if (i < N_NODES) {
        int r = rowoff[i] + bsum[blockIdx.x];
        rowoff[i] = r;
        cursor[i] = r;
    }
    if (i == 0) rowoff[N_NODES] = N_EDGES;
}

__global__ void fill_kernel(const int* __restrict__ src, const int* __restrict__ dst,
                            int* __restrict__ cursor, int* __restrict__ csrsrc)
{
    int e = blockIdx.x * 256 + threadIdx.x;
    if (e >= N_EDGES) return;
    int pos = atomicAdd(&cursor[dst[e]], 1);
    csrsrc[pos] = src[e];
}

// ================= CSR gather-reduce, fp16 source, 128ch, unroll-4 =================
__global__ void __launch_bounds__(256) csr_reduce_h16_128(
    const uint2* __restrict__ x,        // [N_NODES * 32] (each uint2 = 4 halves)
    const int* __restrict__ rowoff,
    const int* __restrict__ csrsrc,
    __half* __restrict__ agg)           // [N_NODES * 128]
{
    int node = (int)((blockIdx.x * 256u + threadIdx.x) >> 5);
    if (node >= N_NODES) return;
    int lane = threadIdx.x & 31;

    float accA[4] = {0, 0, 0, 0};
    float accB[4] = {0, 0, 0, 0};
    h4_add(accA, x[(size_t)node * 32 + lane]);      // self term

    int b = __ldg(&rowoff[node]);
    int e = __ldg(&rowoff[node + 1]);
    for (; b + 3 < e; b += 4) {
        int s0 = __ldg(&csrsrc[b]);
        int s1 = __ldg(&csrsrc[b + 1]);
        int s2 = __ldg(&csrsrc[b + 2]);
        int s3 = __ldg(&csrsrc[b + 3]);
        uint2 v0 = x[(size_t)s0 * 32 + lane];
        uint2 v1 = x[(size_t)s1 * 32 + lane];
        uint2 v2 = x[(size_t)s2 * 32 + lane];
        uint2 v3 = x[(size_t)s3 * 32 + lane];
        h4_add(accA, v0);
        h4_add(accB, v1);
        h4_add(accA, v2);
        h4_add(accB, v3);
    }
    for (; b < e; b++)
        h4_add(accA, x[(size_t)__ldg(&csrsrc[b]) * 32 + lane]);

    uint2 o;
    o.x = pack_h2(accA[0] + accB[0], accA[1] + accB[1]);
    o.y = pack_h2(accA[2] + accB[2], accA[3] + accB[3]);
    *(uint2*)&agg[(size_t)node * 128 + lane * 4] = o;
}

// ================= CSR gather-reduce, fp16 source, 256ch, unroll-4 =================
__global__ void __launch_bounds__(256) csr_reduce_h16_256(
    const uint4* __restrict__ x,        // [N_NODES * 32] (each uint4 = 8 halves)
    const int* __restrict__ rowoff,
    const int* __restrict__ csrsrc,
    __half* __restrict__ agg)           // [N_NODES * 256]
{
    int node = (int)((blockIdx.x * 256u + threadIdx.x) >> 5);
    if (node >= N_NODES) return;
    int lane = threadIdx.x & 31;

    float accA[8] = {0, 0, 0, 0, 0, 0, 0, 0};
    float accB[8] = {0, 0, 0, 0, 0, 0, 0, 0};
    h8_add(accA, x[(size_t)node * 32 + lane]);      // self term

    int b = __ldg(&rowoff[node]);
    int e = __ldg(&rowoff[node + 1]);
    for (; b + 3 < e; b += 4) {
        int s0 = __ldg(&csrsrc[b]);
        int s1 = __ldg(&csrsrc[b + 1]);
        int s2 = __ldg(&csrsrc[b + 2]);
        int s3 = __ldg(&csrsrc[b + 3]);
        uint4 v0 = x[(size_t)s0 * 32 + lane];
        uint4 v1 = x[(size_t)s1 * 32 + lane];
        uint4 v2 = x[(size_t)s2 * 32 + lane];
        uint4 v3 = x[(size_t)s3 * 32 + lane];
        h8_add(accA, v0);
        h8_add(accB, v1);
        h8_add(accA, v2);
        h8_add(accB, v3);
    }
    for (; b < e; b++)
        h8_add(accA, x[(size_t)__ldg(&csrsrc[b]) * 32 + lane]);

    uint4 o;
    o.x = pack_h2(accA[0] + accB[0], accA[1] + accB[1]);
    o.y = pack_h2(accA[2] + accB[2], accA[3] + accB[3]);
    o.z = pack_h2(accA[4] + accB[4], accA[5] + accB[5]);
    o.w = pack_h2(accA[6] + accB[6], accA[7] + accB[7]);
    *(uint4*)&agg[(size_t)node * 256 + lane * 8] = o;
}

// ================= fused 2-layer MLP, fp16 MMA =================
template <int K, int N2, bool OUTER_RELU, bool HALF_OUT>
__global__ void __launch_bounds__(512) fused_mlp(
    const __half* __restrict__ A,      // [M, K] fp16
    const __half* __restrict__ Wp1,    // packed fp16 [K x 256]
    const float* __restrict__ b1v,
    const __half* __restrict__ Wp2,    // packed fp16 [256 x N2]
    const float* __restrict__ b2v,
    void* __restrict__ Cv)
{
    constexpr int BM = 128;
    constexpr int GA = K / 32, GB = HID_C / 32;
    constexpr int NT2 = N2 / 64;
    constexpr int NF  = N2 / 32;
    constexpr int NPL = NF / 2;
    constexpr int M = N_NODES;
    constexpr int AP = 40, HP = 264;
    constexpr int ABUF  = BM * AP;
    constexpr int W1OFF = 2 * ABUF;
    constexpr int WBUF1 = 8192;
    constexpr int W2OFF = BM * HP;
    constexpr int WBUF2 = 32 * N2;

    extern __shared__ __half smh[];
    const uint32_t sbase = smem_u32(smh);

    const int tid  = threadIdx.x;
    const int wid  = tid >> 5;
    const int lane = tid & 31;
    const int gid  = lane >> 2;
    const int tig  = lane & 3;
    const int wm   = wid & 3;
    const int wn   = wid >> 2;
    const int rA   = wm * 32;
    const int m0   = blockIdx.x * BM;

    float acc[2][8][4];
#pragma unroll
    for (int i = 0; i < 2; i++)
#pragma unroll
        for (int j = 0; j < 8; j++)
#pragma unroll
            for (int c = 0; c < 4; c++) acc[i][j][c] = 0.0f;

    auto loadA = [&](int g) {
        const int s = g & 1;
        {
            int row = tid >> 2, c4 = tid & 3;
            cp_async16(sbase + (uint32_t)(s * ABUF + row * AP + c4 * 8) * 2u,
                       A + (size_t)(m0 + row) * K + g * 32 + c4 * 8,
                       (m0 + row) < M);
        }
#pragma unroll
        for (int j = 0; j < 2; j++) {
            int idx = j * 512 + tid;
            cp_async16(sbase + (uint32_t)(W1OFF + s * WBUF1 + idx * 8) * 2u,
                       Wp1 + (size_t)g * WBUF1 + idx * 8, true);
        }
        CP_COMMIT();
    };
    auto loadB = [&](int g) {
        const int s = g & 1;
#pragma unroll
        for (int j = 0; j < WBUF2 / 8 / 512; j++) {
            int idx = j * 512 + tid;
            cp_async16(sbase + (uint32_t)(W2OFF + s * WBUF2 + idx * 8) * 2u,
                       Wp2 + (size_t)g * WBUF2 + idx * 8, true);
        }
        CP_COMMIT();
    };

    // ---- phase A: Hacc = A @ W1 ----
    loadA(0);
    for (int g = 0; g < GA; g++) {
        if (g + 1 < GA) { loadA(g + 1); CP_WAIT(1); }
        else            { CP_WAIT(0); }
        __syncthreads();
        const __half* ah = smh + (g & 1) * ABUF;
        const float4* bf = (const float4*)(smh + W1OFF + (g & 1) * WBUF1);
#pragma unroll
        for (int ks = 0; ks < 2; ks++) {
            const int k0 = ks * 16 + 2 * tig;
            uint32_t a[2][4];
#pragma unroll
            for (int mf = 0; mf < 2; mf++) {
                int base = rA + mf * 16;
                a[mf][0] = *(const uint32_t*)&ah[(base + gid)     * AP + k0];
                a[mf][1] = *(const uint32_t*)&ah[(base + gid + 8) * AP + k0];
                a[mf][2] = *(const uint32_t*)&ah[(base + gid)     * AP + k0 + 8];
                a[mf][3] = *(const uint32_t*)&ah[(base + gid + 8) * AP + k0 + 8];
            }
            uint32_t b[8][2];
#pragma unroll
            for (int p = 0; p < 4; p++) {
                float4 q = bf[((ks * 4 + wn) * 4 + p) * 32 + lane];
                b[2 * p][0]     = __float_as_uint(q.x);
                b[2 * p][1]     = __float_as_uint(q.y);
                b[2 * p + 1][0] = __float_as_uint(q.z);
                b[2 * p + 1][1] = __float_as_uint(q.w);
            }
#pragma unroll
            for (int mf = 0; mf < 2; mf++)
#pragma unroll
                for (int nf = 0; nf < 8; nf++)
                    mma_f16(acc[mf][nf], a[mf][0], a[mf][1], a[mf][2], a[mf][3],
                            b[nf][0], b[nf][1]);
        }
        __syncthreads();
    }

    loadB(0);

    // ---- spill H = fp16(relu(acc + b1)) into smem ----
#pragma unroll
    for (int nf = 0; nf < 8; nf++) {
        int col = wn * 64 + nf * 8 + tig * 2;
        float c0 = b1v[col], c1 = b1v[col + 1];
#pragma unroll
        for (int mf = 0; mf < 2; mf++) {
            int r0 = rA + mf * 16 + gid;
            *(uint32_t*)&smh[(size_t)r0 * HP + col] =
                pack_h2(fmaxf(acc[mf][nf][0] + c0, 0.f), fmaxf(acc[mf][nf][1] + c1, 0.f));
            *(uint32_t*)&smh[(size_t)(r0 + 8) * HP + col] =
                pack_h2(fmaxf(acc[mf][nf][2] + c0, 0.f), fmaxf(acc[mf][nf][3] + c1, 0.f));
        }
    }
#pragma unroll
    for (int i = 0; i < 2; i++)
#pragma unroll
        for (int j = 0; j < 8; j++)
#pragma unroll
            for (int c = 0; c < 4; c++) acc[i][j][c] = 0.0f;

    // ---- phase 4: OUT = H @ W2 ----
    const int grp = (NF == 8) ? wn : (wn >> 1);
    for (int g = 0; g < GB; g++) {
        if (g + 1 < GB) { loadB(g + 1); CP_WAIT(1); }
        else            { CP_WAIT(0); }
        __syncthreads();
        const float4* bf = (const float4*)(smh + W2OFF + (g & 1) * WBUF2);
#pragma unroll
        for (int ks = 0; ks < 2; ks++) {
            const int k0 = g * 32 + ks * 16 + 2 * tig;
            uint32_t a[2][4];
#pragma unroll
            for (int mf = 0; mf < 2; mf++) {
                int base = rA + mf * 16;
                a[mf][0] = *(const uint32_t*)&smh[(size_t)(base + gid)     * HP + k0];
                a[mf][1] = *(const uint32_t*)&smh[(size_t)(base + gid + 8) * HP + k0];
                a[mf][2] = *(const uint32_t*)&smh[(size_t)(base + gid)     * HP + k0 + 8];
                a[mf][3] = *(const uint32_t*)&smh[(size_t)(base + gid + 8) * HP + k0 + 8];
            }
            uint32_t b[8][2];
#pragma unroll
            for (int pl = 0; pl < NPL; pl++) {
                int p = (NF == 8) ? pl : (2 * (wn & 1) + pl);
                float4 q = bf[((ks * NT2 + grp) * 4 + p) * 32 + lane];
                b[2 * pl][0]     = __float_as_uint(q.x);
                b[2 * pl][1]     = __float_as_uint(q.y);
                b[2 * pl + 1][0] = __float_as_uint(q.z);
                b[2 * pl + 1][1] = __float_as_uint(q.w);
            }
#pragma unroll
            for (int mf = 0; mf < 2; mf++)
#pragma unroll
                for (int nf = 0; nf < NF; nf++)
                    mma_f16(acc[mf][nf], a[mf][0], a[mf][1], a[mf][2], a[mf][3],
                            b[nf][0], b[nf][1]);
        }
        __syncthreads();
    }

    // ---- epilogue ----
#pragma unroll
    for (int nf = 0; nf < NF; nf++) {
        int col = wn * (N2 / 4) + nf * 8 + tig * 2;
        float c0 = b2v[col], c1 = b2v[col + 1];
#pragma unroll
        for (int mf = 0; mf < 2; mf++) {
            int r0 = m0 + rA + mf * 16 + gid;
            float v0 = acc[mf][nf][0] + c0, v1 = acc[mf][nf][1] + c1;
            float v2 = acc[mf][nf][2] + c0, v3 = acc[mf][nf][3] + c1;
            if (OUTER_RELU) {
                v0 = fmaxf(v0, 0.f); v1 = fmaxf(v1, 0.f);
                v2 = fmaxf(v2, 0.f); v3 = fmaxf(v3, 0.f);
            }
            if (HALF_OUT) {
                __half* Ch = (__half*)Cv;
                if (r0 < M)
                    *(uint32_t*)&Ch[(size_t)r0 * N2 + col] = pack_h2(v0, v1);
                if (r0 + 8 < M)
                    *(uint32_t*)&Ch[(size_t)(r0 + 8) * N2 + col] = pack_h2(v2, v3);
            } else {
                float* Cf = (float*)Cv;
                if (r0 < M)
                    *(float2*)&Cf[(size_t)r0 * N2 + col] = make_float2(v0, v1);
                if (r0 + 8 < M)
                    *(float2*)&Cf[(size_t)(r0 + 8) * N2 + col] = make_float2(v2, v3);
            }
        }
    }
}

// ================= launch =================
extern "C" void kernel_launch(void* const* d_in, const int* in_sizes, int n_in,
                              void* d_out, int out_size)
{
    const float* x   = (const float*)d_in[0];
    const int*   ei  = (const int*)d_in[1];
    const float* W1a = (const float*)d_in[2];
    const float* b1a = (const float*)d_in[3];
    const float* W2a = (const float*)d_in[4];
    const float* b2a = (const float*)d_in[5];
    const float* W1b = (const float*)d_in[6];
    const float* b1b = (const float*)d_in[7];
    const float* W2b = (const float*)d_in[8];
    const float* b2b = (const float*)d_in[9];
    float* out = (float*)d_out;

    __half *xh, *agg1, *h, *agg2, *Wf1, *Wf2, *Wf3, *Wf4;
    int *cnt, *rowoff, *cursor, *csrsrc, *bsum;
    cudaGetSymbolAddress((void**)&xh,   g_xh);
    cudaGetSymbolAddress((void**)&agg1, g_agg1);
    cudaGetSymbolAddress((void**)&h,    g_h);
    cudaGetSymbolAddress((void**)&agg2, g_agg2);
    cudaGetSymbolAddress((void**)&Wf1,  g_Wf1);
    cudaGetSymbolAddress((void**)&Wf2,  g_Wf2);
    cudaGetSymbolAddress((void**)&Wf3,  g_Wf3);
    cudaGetSymbolAddress((void**)&Wf4,  g_Wf4);
    cudaGetSymbolAddress((void**)&cnt,    g_cnt);
    cudaGetSymbolAddress((void**)&rowoff, g_rowoff);
    cudaGetSymbolAddress((void**)&cursor, g_cursor);
    cudaGetSymbolAddress((void**)&csrsrc, g_csrsrc);
    cudaGetSymbolAddress((void**)&bsum,   g_bsum);

    const int* src = ei;
    const int* dst = ei + N_EDGES;

    const int mTiles = (N_NODES + 127) / 128;      // 782
    const int eBlocks = (N_EDGES + 255) / 256;
    const int nWarpBlocks = (N_NODES * 32 + 255) / 256;

    const int SM1 = (128 * 264 + 2 * 32 * HID_C) * 2;   // 100352 B
    const int SM2 = (128 * 264 + 2 * 32 * OUT_C) * 2;   //  83968 B
    cudaFuncSetAttribute(fused_mlp<IN_C,  HID_C, true,  true >,
                         cudaFuncAttributeMaxDynamicSharedMemorySize, SM1);
    cudaFuncSetAttribute(fused_mlp<HID_C, OUT_C, false, false>,
                         cudaFuncAttributeMaxDynamicSharedMemorySize, SM2);

    // ---- x -> fp16 ----
    {
        int n8 = N_NODES * IN_C / 8;   // 1.6M uint4s
        convert_kernel<<<(n8 + 255) / 256, 256>>>((const float4*)x, (uint4*)xh, n8);
    }

    // ---- CSR build (dst-sorted) ----
    cudaMemsetAsync(cnt, 0, N_NODES * sizeof(int));
    hist_kernel<<<eBlocks, 256>>>(dst, cnt);
    scan1_kernel<<<SCAN_NB, 1024>>>(cnt, rowoff, bsum);
    scan2_kernel<<<1, 128>>>(bsum);
    scan3_kernel<<<SCAN_NB, 1024>>>(rowoff, bsum, cursor);
    fill_kernel<<<eBlocks, 256>>>(src, dst, cursor, csrsrc);

    // ---- weight fragment packs (fp16) ----
    pack_kernel<IN_C,  HID_C><<<(IN_C * HID_C / 8 + 255) / 256, 256>>>(W1a, Wf1);
    pack_kernel<HID_C, HID_C><<<(HID_C * HID_C / 8 + 255) / 256, 256>>>(W2a, Wf2);
    pack_kernel<HID_C, HID_C><<<(HID_C * HID_C / 8 + 255) / 256, 256>>>(W1b, Wf3);
    pack_kernel<HID_C, OUT_C><<<(HID_C * OUT_C / 8 + 255) / 256, 256>>>(W2b, Wf4);

    // ---- conv1: reduce (fp16 x -> fp16 agg) + fused MLP (fp16 h out) ----
    csr_reduce_h16_128<<<nWarpBlocks, 256>>>(
        (const uint2*)xh, rowoff, csrsrc, agg1);
    fused_mlp<IN_C, HID_C, true, true><<<mTiles, 512, SM1>>>(
        agg1, Wf1, b1a, Wf2, b2a, h);

    // ---- conv2: reduce (fp16 h -> fp16 agg) + fused MLP (fp32 out) ----
    csr_reduce_h16_256<<<nWarpBlocks, 256>>>(
        (const uint4*)h, rowoff, csrsrc, agg2);
    fused_mlp<HID_C, OUT_C, false, false><<<mTiles, 512, SM2>>>(
        agg2, Wf3, b1b, Wf4, b2b, out);
}

// round 16
// speedup vs baseline: 1.4939x; 1.4939x over previous
#include <cuda_runtime.h>
#include <cuda_fp16.h>
#include <cstdint>

#define N_NODES 100000
#define N_EDGES 1600000
#define IN_C 128
#define HID_C 256
#define OUT_C 128
#define SCAN_NB ((N_NODES + 1023) / 1024)   // 98

// ================= scratch =================
__device__ __half  g_xh  [N_NODES * IN_C];       // fp16 copy of x
__device__ __half  g_agg1[N_NODES * IN_C];       // fp16 aggregated input (conv1)
__device__ __half  g_h   [N_NODES * HID_C];      // conv1 output (fp16, relu)
__device__ __half  g_agg2[N_NODES * HID_C];      // fp16 aggregated input (conv2)
__device__ __half  g_Wf1[IN_C * HID_C];          // fragment-packed fp16 weights
__device__ __half  g_Wf2[HID_C * HID_C];
__device__ __half  g_Wf3[HID_C * HID_C];
__device__ __half  g_Wf4[HID_C * OUT_C];
__device__ int     g_cnt[N_NODES];
__device__ int     g_rowoff[N_NODES + 1];
__device__ int     g_cursor[N_NODES];
__device__ int     g_csrsrc[N_EDGES];
__device__ int     g_bsum[SCAN_NB];

// ================= helpers =================
__device__ __forceinline__ uint32_t smem_u32(const void* p) {
    uint32_t a;
    asm("{ .reg .u64 t; cvta.to.shared.u64 t, %1; cvt.u32.u64 %0, t; }" : "=r"(a) : "l"(p));
    return a;
}
__device__ __forceinline__ void cp_async16(uint32_t dst, const void* src, bool pred) {
    int sz = pred ? 16 : 0;
    asm volatile("cp.async.ca.shared.global [%0], [%1], 16, %2;"
                 :: "r"(dst), "l"(src), "r"(sz) : "memory");
}
#define CP_COMMIT() asm volatile("cp.async.commit_group;" ::: "memory")
#define CP_WAIT(n)  asm volatile("cp.async.wait_group %0;" :: "n"(n) : "memory")

__device__ __forceinline__ void mma_f16(float* d, uint32_t a0, uint32_t a1,
                                        uint32_t a2, uint32_t a3,
                                        uint32_t b0, uint32_t b1) {
    asm volatile(
        "mma.sync.aligned.m16n8k16.row.col.f32.f16.f16.f32 "
        "{%0,%1,%2,%3}, {%4,%5,%6,%7}, {%8,%9}, {%0,%1,%2,%3};"
        : "+f"(d[0]), "+f"(d[1]), "+f"(d[2]), "+f"(d[3])
        : "r"(a0), "r"(a1), "r"(a2), "r"(a3), "r"(b0), "r"(b1));
}
__device__ __forceinline__ uint32_t pack_h2(float lo, float hi) {
    __half2 h = __floats2half2_rn(lo, hi);
    return *(uint32_t*)&h;
}
__device__ __forceinline__ void h8_add(float* acc, uint4 v) {
    float2 f;
    f = __half22float2(*(__half2*)&v.x); acc[0] += f.x; acc[1] += f.y;
    f = __half22float2(*(__half2*)&v.y); acc[2] += f.x; acc[3] += f.y;
    f = __half22float2(*(__half2*)&v.z); acc[4] += f.x; acc[5] += f.y;
    f = __half22float2(*(__half2*)&v.w); acc[6] += f.x; acc[7] += f.y;
}
__device__ __forceinline__ void h4_add(float* acc, uint2 v) {
    float2 f;
    f = __half22float2(*(__half2*)&v.x); acc[0] += f.x; acc[1] += f.y;
    f = __half22float2(*(__half2*)&v.y); acc[2] += f.x; acc[3] += f.y;
}

// ================= x -> fp16 convert =================
__global__ void convert_kernel(const float4* __restrict__ x, uint4* __restrict__ xh, int n8)
{
    int i = blockIdx.x * 256 + threadIdx.x;
    if (i >= n8) return;
    float4 a = x[2 * i], b = x[2 * i + 1];
    uint4 o;
    o.x = pack_h2(a.x, a.y);
    o.y = pack_h2(a.z, a.w);
    o.z = pack_h2(b.x, b.y);
    o.w = pack_h2(b.z, b.w);
    xh[i] = o;
}

// ================= weight fragment-pack (fp16) =================
template <int K, int NTOT>
__global__ void pack_kernel(const float* __restrict__ W, __half* __restrict__ Wf)
{
    constexpr int NT = NTOT / 64;
    constexpr int PER_G = 4 * NTOT;             // uint4s per 32-k chunk
    int id = blockIdx.x * 256 + threadIdx.x;
    if (id >= K * NTOT / 8) return;
    int q  = id % PER_G;
    int g  = id / PER_G;
    int lane = q & 31;
    int p    = (q >> 5) & 3;
    int rest = q >> 7;
    int wt   = rest % NT;
    int ks   = rest / NT;

    int gid = lane >> 2, tig = lane & 3;
    int n0 = wt * 64 + 2 * p * 8 + gid;
    int k0 = g * 32 + ks * 16 + tig * 2;

    uint4 v;
    v.x = pack_h2(W[(size_t)k0       * NTOT + n0],     W[(size_t)(k0 + 1) * NTOT + n0]);
    v.y = pack_h2(W[(size_t)(k0 + 8) * NTOT + n0],     W[(size_t)(k0 + 9) * NTOT + n0]);
    v.z = pack_h2(W[(size_t)k0       * NTOT + n0 + 8], W[(size_t)(k0 + 1) * NTOT + n0 + 8]);
    v.w = pack_h2(W[(size_t)(k0 + 8) * NTOT + n0 + 8], W[(size_t)(k0 + 9) * NTOT + n0 + 8]);
    *(uint4*)&Wf[(size_t)id * 8] = v;
}

// ================= CSR build =================
__global__ void hist_kernel(const int* __restrict__ dst, int* __restrict__ cnt)
{
    int e = blockIdx.x * 256 + threadIdx.x;
    if (e < N_EDGES) atomicAdd(&cnt[dst[e]], 1);
}

__global__ void scan1_kernel(const int* __restrict__ cnt, int* __restrict__ rowoff,
                             int* __restrict__ bsum)
{
    __shared__ int sh[1024];
    int tid = threadIdx.x;
    int i = blockIdx.x * 1024 + tid;
    int v = (i < N_NODES) ? cnt[i] : 0;
    sh[tid] = v;
    __syncthreads();
#pragma unroll
    for (int off = 1; off < 1024; off <<= 1) {
        int t = (tid >= off) ? sh[tid - off] : 0;
        __syncthreads();
        sh[tid] += t;
        __syncthreads();
    }
    if (i < N_NODES) rowoff[i] = sh[tid] - v;
    if (tid == 1023) bsum[blockIdx.x] = sh[tid];
}

__global__ void scan2_kernel(int* __restrict__ bsum)
{
    __shared__ int sh[128];
    int tid = threadIdx.x;
    int v = (tid < SCAN_NB) ? bsum[tid] : 0;
    sh[tid] = v;
    __syncthreads();
#pragma unroll
    for (int off = 1; off < 128; off <<= 1) {
        int t = (tid >= off) ? sh[tid - off] : 0;
        __syncthreads();
        sh[tid] += t;
        __syncthreads();
    }
    if (tid < SCAN_NB) bsum[tid] = sh[tid] - v;
}

__global__ void scan3_kernel(int* __restrict__ rowoff, const int* __restrict__ bsum,
                             int* __restrict__ cursor)
{
    int i = blockIdx.x * 1024 + threadIdx.x;
    if (i < N_NODES) {
        int r = rowoff[i] + bsum[blockIdx.x];
        rowoff[i] = r;
        cursor[i] = r;
    }
    if (i == 0) rowoff[N_NODES] = N_EDGES;
}

__global__ void fill_kernel(const int* __restrict__ src, const int* __restrict__ dst,
                            int* __restrict__ cursor, int* __restrict__ csrsrc)
{
    int e = blockIdx.x * 256 + threadIdx.x;
    if (e >= N_EDGES) return;
    int pos = atomicAdd(&cursor[dst[e]], 1);
    csrsrc[pos] = src[e];
}

// ================= CSR gather-reduce, fp16 source, 128ch =================
// unroll-4 loads, SINGLE accumulator (register-cheap), occupancy pinned
__global__ void __launch_bounds__(256, 6) csr_reduce_h16_128(
    const uint2* __restrict__ x,        // [N_NODES * 32] (each uint2 = 4 halves)
    const int* __restrict__ rowoff,
    const int* __restrict__ csrsrc,
    __half* __restrict__ agg)           // [N_NODES * 128]
{
    int node = (int)((blockIdx.x * 256u + threadIdx.x) >> 5);
    if (node >= N_NODES) return;
    int lane = threadIdx.x & 31;

    float acc[4] = {0, 0, 0, 0};
    h4_add(acc, x[(size_t)node * 32 + lane]);       // self term

    int b = __ldg(&rowoff[node]);
    int e = __ldg(&rowoff[node + 1]);
    for (; b + 3 < e; b += 4) {
        int s0 = __ldg(&csrsrc[b]);
        int s1 = __ldg(&csrsrc[b + 1]);
        int s2 = __ldg(&csrsrc[b + 2]);
        int s3 = __ldg(&csrsrc[b + 3]);
        uint2 v0 = x[(size_t)s0 * 32 + lane];
        uint2 v1 = x[(size_t)s1 * 32 + lane];
        uint2 v2 = x[(size_t)s2 * 32 + lane];
        uint2 v3 = x[(size_t)s3 * 32 + lane];
        h4_add(acc, v0);
        h4_add(acc, v1);
        h4_add(acc, v2);
        h4_add(acc, v3);
    }
    for (; b < e; b++)
        h4_add(acc, x[(size_t)__ldg(&csrsrc[b]) * 32 + lane]);

    uint2 o;
    o.x = pack_h2(acc[0], acc[1]);
    o.y = pack_h2(acc[2], acc[3]);
    *(uint2*)&agg[(size_t)node * 128 + lane * 4] = o;
}

// ================= CSR gather-reduce, fp16 source, 256ch =================
__global__ void __launch_bounds__(256, 6) csr_reduce_h16_256(
    const uint4* __restrict__ x,        // [N_NODES * 32] (each uint4 = 8 halves)
    const int* __restrict__ rowoff,
    const int* __restrict__ csrsrc,
    __half* __restrict__ agg)           // [N_NODES * 256]
{
    int node = (int)((blockIdx.x * 256u + threadIdx.x) >> 5);
    if (node >= N_NODES) return;
    int lane = threadIdx.x & 31;

    float acc[8] = {0, 0, 0, 0, 0, 0, 0, 0};
    h8_add(acc, x[(size_t)node * 32 + lane]);       // self term

    int b = __ldg(&rowoff[node]);
    int e = __ldg(&rowoff[node + 1]);
    for (; b + 3 < e; b += 4) {
        int s0 = __ldg(&csrsrc[b]);
        int s1 = __ldg(&csrsrc[b + 1]);
        int s2 = __ldg(&csrsrc[b + 2]);
        int s3 = __ldg(&csrsrc[b + 3]);
        uint4 v0 = x[(size_t)s0 * 32 + lane];
        uint4 v1 = x[(size_t)s1 * 32 + lane];
        uint4 v2 = x[(size_t)s2 * 32 + lane];
        uint4 v3 = x[(size_t)s3 * 32 + lane];
        h8_add(acc, v0);
        h8_add(acc, v1);
        h8_add(acc, v2);
        h8_add(acc, v3);
    }
    for (; b < e; b++)
        h8_add(acc, x[(size_t)__ldg(&csrsrc[b]) * 32 + lane]);

    uint4 o;
    o.x = pack_h2(acc[0], acc[1]);
    o.y = pack_h2(acc[2], acc[3]);
    o.z = pack_h2(acc[4], acc[5]);
    o.w = pack_h2(acc[6], acc[7]);
    *(uint4*)&agg[(size_t)node * 256 + lane * 8] = o;
}

// ================= fused 2-layer MLP, fp16 MMA (unchanged from R14) =================
template <int K, int N2, bool OUTER_RELU, bool HALF_OUT>
__global__ void __launch_bounds__(512) fused_mlp(
    const __half* __restrict__ A,      // [M, K] fp16
    const __half* __restrict__ Wp1,    // packed fp16 [K x 256]
    const float* __restrict__ b1v,
    const __half* __restrict__ Wp2,    // packed fp16 [256 x N2]
    const float* __restrict__ b2v,
    void* __restrict__ Cv)
{
    constexpr int BM = 128;
    constexpr int GA = K / 32, GB = HID_C / 32;
    constexpr int NT2 = N2 / 64;
    constexpr int NF  = N2 / 32;
    constexpr int NPL = NF / 2;
    constexpr int M = N_NODES;
    constexpr int AP = 40, HP = 264;
    constexpr int ABUF  = BM * AP;
    constexpr int W1OFF = 2 * ABUF;
    constexpr int WBUF1 = 8192;
    constexpr int W2OFF = BM * HP;
    constexpr int WBUF2 = 32 * N2;

    extern __shared__ __half smh[];
    const uint32_t sbase = smem_u32(smh);

    const int tid  = threadIdx.x;
    const int wid  = tid >> 5;
    const int lane = tid & 31;
    const int gid  = lane >> 2;
    const int tig  = lane & 3;
    const int wm   = wid & 3;
    const int wn   = wid >> 2;
    const int rA   = wm * 32;
    const int m0   = blockIdx.x * BM;

    float acc[2][8][4];
#pragma unroll
    for (int i = 0; i < 2; i++)
#pragma unroll
        for (int j = 0; j < 8; j++)
#pragma unroll
            for (int c = 0; c < 4; c++) acc[i][j][c] = 0.0f;

    auto loadA = [&](int g) {
        const int s = g & 1;
        {
            int row = tid >> 2, c4 = tid & 3;
            cp_async16(sbase + (uint32_t)(s * ABUF + row * AP + c4 * 8) * 2u,
                       A + (size_t)(m0 + row) * K + g * 32 + c4 * 8,
                       (m0 + row) < M);
        }
#pragma unroll
        for (int j = 0; j < 2; j++) {
            int idx = j * 512 + tid;
            cp_async16(sbase + (uint32_t)(W1OFF + s * WBUF1 + idx * 8) * 2u,
                       Wp1 + (size_t)g * WBUF1 + idx * 8, true);
        }
        CP_COMMIT();
    };
    auto loadB = [&](int g) {
        const int s = g & 1;
#pragma unroll
        for (int j = 0; j < WBUF2 / 8 / 512; j++) {
            int idx = j * 512 + tid;
            cp_async16(sbase + (uint32_t)(W2OFF + s * WBUF2 + idx * 8) * 2u,
                       Wp2 + (size_t)g * WBUF2 + idx * 8, true);
        }
        CP_COMMIT();
    };

    // ---- phase A: Hacc = A @ W1 ----
    loadA(0);
    for (int g = 0; g < GA; g++) {
        if (g + 1 < GA) { loadA(g + 1); CP_WAIT(1); }
        else            { CP_WAIT(0); }
        __syncthreads();
        const __half* ah = smh + (g & 1) * ABUF;
        const float4* bf = (const float4*)(smh + W1OFF + (g & 1) * WBUF1);
#pragma unroll
        for (int ks = 0; ks < 2; ks++) {
            const int k0 = ks * 16 + 2 * tig;
            uint32_t a[2][4];
#pragma unroll
            for (int mf = 0; mf < 2; mf++) {
                int base = rA + mf * 16;
                a[mf][0] = *(const uint32_t*)&ah[(base + gid)     * AP + k0];
                a[mf][1] = *(const uint32_t*)&ah[(base + gid + 8) * AP + k0];
                a[mf][2] = *(const uint32_t*)&ah[(base + gid)     * AP + k0 + 8];
                a[mf][3] = *(const uint32_t*)&ah[(base + gid + 8) * AP + k0 + 8];
            }
            uint32_t b[8][2];
#pragma unroll
            for (int p = 0; p < 4; p++) {
                float4 q = bf[((ks * 4 + wn) * 4 + p) * 32 + lane];
                b[2 * p][0]     = __float_as_uint(q.x);
                b[2 * p][1]     = __float_as_uint(q.y);
                b[2 * p + 1][0] = __float_as_uint(q.z);
                b[2 * p + 1][1] = __float_as_uint(q.w);
            }
#pragma unroll
            for (int mf = 0; mf < 2; mf++)
#pragma unroll
                for (int nf = 0; nf < 8; nf++)
                    mma_f16(acc[mf][nf], a[mf][0], a[mf][1], a[mf][2], a[mf][3],
                            b[nf][0], b[nf][1]);
        }
        __syncthreads();
    }

    loadB(0);

    // ---- spill H = fp16(relu(acc + b1)) into smem ----
#pragma unroll
    for (int nf = 0; nf < 8; nf++) {
        int col = wn * 64 + nf * 8 + tig * 2;
        float c0 = b1v[col], c1 = b1v[col + 1];
#pragma unroll
        for (int mf = 0; mf < 2; mf++) {
            int r0 = rA + mf * 16 + gid;
            *(uint32_t*)&smh[(size_t)r0 * HP + col] =
                pack_h2(fmaxf(acc[mf][nf][0] + c0, 0.f), fmaxf(acc[mf][nf][1] + c1, 0.f));
            *(uint32_t*)&smh[(size_t)(r0 + 8) * HP + col] =
                pack_h2(fmaxf(acc[mf][nf][2] + c0, 0.f), fmaxf(acc[mf][nf][3] + c1, 0.f));
        }
    }
#pragma unroll
    for (int i = 0; i < 2; i++)
#pragma unroll
        for (int j = 0; j < 8; j++)
#pragma unroll
            for (int c = 0; c < 4; c++) acc[i][j][c] = 0.0f;

    // ---- phase 4: OUT = H @ W2 ----
    const int grp = (NF == 8) ? wn : (wn >> 1);
    for (int g = 0; g < GB; g++) {
        if (g + 1 < GB) { loadB(g + 1); CP_WAIT(1); }
        else            { CP_WAIT(0); }
        __syncthreads();
        const float4* bf = (const float4*)(smh + W2OFF + (g & 1) * WBUF2);
#pragma unroll
        for (int ks = 0; ks < 2; ks++) {
            const int k0 = g * 32 + ks * 16 + 2 * tig;
            uint32_t a[2][4];
#pragma unroll
            for (int mf = 0; mf < 2; mf++) {
                int base = rA + mf * 16;
                a[mf][0] = *(const uint32_t*)&smh[(size_t)(base + gid)     * HP + k0];
                a[mf][1] = *(const uint32_t*)&smh[(size_t)(base + gid + 8) * HP + k0];
                a[mf][2] = *(const uint32_t*)&smh[(size_t)(base + gid)     * HP + k0 + 8];
                a[mf][3] = *(const uint32_t*)&smh[(size_t)(base + gid + 8) * HP + k0 + 8];
            }
            uint32_t b[8][2];
#pragma unroll
            for (int pl = 0; pl < NPL; pl++) {
                int p = (NF == 8) ? pl : (2 * (wn & 1) + pl);
                float4 q = bf[((ks * NT2 + grp) * 4 + p) * 32 + lane];
                b[2 * pl][0]     = __float_as_uint(q.x);
                b[2 * pl][1]     = __float_as_uint(q.y);
                b[2 * pl + 1][0] = __float_as_uint(q.z);
                b[2 * pl + 1][1] = __float_as_uint(q.w);
            }
#pragma unroll
            for (int mf = 0; mf < 2; mf++)
#pragma unroll
                for (int nf = 0; nf < NF; nf++)
                    mma_f16(acc[mf][nf], a[mf][0], a[mf][1], a[mf][2], a[mf][3],
                            b[nf][0], b[nf][1]);
        }
        __syncthreads();
    }

    // ---- epilogue ----
#pragma unroll
    for (int nf = 0; nf < NF; nf++) {
        int col = wn * (N2 / 4) + nf * 8 + tig * 2;
        float c0 = b2v[col], c1 = b2v[col + 1];
#pragma unroll
        for (int mf = 0; mf < 2; mf++) {
            int r0 = m0 + rA + mf * 16 + gid;
            float v0 = acc[mf][nf][0] + c0, v1 = acc[mf][nf][1] + c1;
            float v2 = acc[mf][nf][2] + c0, v3 = acc[mf][nf][3] + c1;
            if (OUTER_RELU) {
                v0 = fmaxf(v0, 0.f); v1 = fmaxf(v1, 0.f);
                v2 = fmaxf(v2, 0.f); v3 = fmaxf(v3, 0.f);
            }
            if (HALF_OUT) {
                __half* Ch = (__half*)Cv;
                if (r0 < M)
                    *(uint32_t*)&Ch[(size_t)r0 * N2 + col] = pack_h2(v0, v1);
                if (r0 + 8 < M)
                    *(uint32_t*)&Ch[(size_t)(r0 + 8) * N2 + col] = pack_h2(v2, v3);
            } else {
                float* Cf = (float*)Cv;
                if (r0 < M)
                    *(float2*)&Cf[(size_t)r0 * N2 + col] = make_float2(v0, v1);
                if (r0 + 8 < M)
                    *(float2*)&Cf[(size_t)(r0 + 8) * N2 + col] = make_float2(v2, v3);
            }
        }
    }
}

// ================= launch =================
extern "C" void kernel_launch(void* const* d_in, const int* in_sizes, int n_in,
                              void* d_out, int out_size)
{
    const float* x   = (const float*)d_in[0];
    const int*   ei  = (const int*)d_in[1];
    const float* W1a = (const float*)d_in[2];
    const float* b1a = (const float*)d_in[3];
    const float* W2a = (const float*)d_in[4];
    const float* b2a = (const float*)d_in[5];
    const float* W1b = (const float*)d_in[6];
    const float* b1b = (const float*)d_in[7];
    const float* W2b = (const float*)d_in[8];
    const float* b2b = (const float*)d_in[9];
    float* out = (float*)d_out;

    __half *xh, *agg1, *h, *agg2, *Wf1, *Wf2, *Wf3, *Wf4;
    int *cnt, *rowoff, *cursor, *csrsrc, *bsum;
    cudaGetSymbolAddress((void**)&xh,   g_xh);
    cudaGetSymbolAddress((void**)&agg1, g_agg1);
    cudaGetSymbolAddress((void**)&h,    g_h);
    cudaGetSymbolAddress((void**)&agg2, g_agg2);
    cudaGetSymbolAddress((void**)&Wf1,  g_Wf1);
    cudaGetSymbolAddress((void**)&Wf2,  g_Wf2);
    cudaGetSymbolAddress((void**)&Wf3,  g_Wf3);
    cudaGetSymbolAddress((void**)&Wf4,  g_Wf4);
    cudaGetSymbolAddress((void**)&cnt,    g_cnt);
    cudaGetSymbolAddress((void**)&rowoff, g_rowoff);
    cudaGetSymbolAddress((void**)&cursor, g_cursor);
    cudaGetSymbolAddress((void**)&csrsrc, g_csrsrc);
    cudaGetSymbolAddress((void**)&bsum,   g_bsum);

    const int* src = ei;
    const int* dst = ei + N_EDGES;

    const int mTiles = (N_NODES + 127) / 128;      // 782
    const int eBlocks = (N_EDGES + 255) / 256;
    const int nWarpBlocks = (N_NODES * 32 + 255) / 256;

    const int SM1 = (128 * 264 + 2 * 32 * HID_C) * 2;   // 100352 B
    const int SM2 = (128 * 264 + 2 * 32 * OUT_C) * 2;   //  83968 B
    cudaFuncSetAttribute(fused_mlp<IN_C,  HID_C, true,  true >,
                         cudaFuncAttributeMaxDynamicSharedMemorySize, SM1);
    cudaFuncSetAttribute(fused_mlp<HID_C, OUT_C, false, false>,
                         cudaFuncAttributeMaxDynamicSharedMemorySize, SM2);

    // ---- x -> fp16 ----
    {
        int n8 = N_NODES * IN_C / 8;   // 1.6M uint4s
        convert_kernel<<<(n8 + 255) / 256, 256>>>((const float4*)x, (uint4*)xh, n8);
    }

    // ---- CSR build (dst-sorted) ----
    cudaMemsetAsync(cnt, 0, N_NODES * sizeof(int));
    hist_kernel<<<eBlocks, 256>>>(dst, cnt);
    scan1_kernel<<<SCAN_NB, 1024>>>(cnt, rowoff, bsum);
    scan2_kernel<<<1, 128>>>(bsum);
    scan3_kernel<<<SCAN_NB, 1024>>>(rowoff, bsum, cursor);
    fill_kernel<<<eBlocks, 256>>>(src, dst, cursor, csrsrc);

    // ---- weight fragment packs (fp16) ----
    pack_kernel<IN_C,  HID_C><<<(IN_C * HID_C / 8 + 255) / 256, 256>>>(W1a, Wf1);
    pack_kernel<HID_C, HID_C><<<(HID_C * HID_C / 8 + 255) / 256, 256>>>(W2a, Wf2);
    pack_kernel<HID_C, HID_C><<<(HID_C * HID_C / 8 + 255) / 256, 256>>>(W1b, Wf3);
    pack_kernel<HID_C, OUT_C><<<(HID_C * OUT_C / 8 + 255) / 256, 256>>>(W2b, Wf4);

    // ---- conv1: reduce (fp16 x -> fp16 agg) + fused MLP (fp16 h out) ----
    csr_reduce_h16_128<<<nWarpBlocks, 256>>>(
        (const uint2*)xh, rowoff, csrsrc, agg1);
    fused_mlp<IN_C, HID_C, true, true><<<mTiles, 512, SM1>>>(
        agg1, Wf1, b1a, Wf2, b2a, h);

    // ---- conv2: reduce (fp16 h -> fp16 agg) + fused MLP (fp32 out) ----
    csr_reduce_h16_256<<<nWarpBlocks, 256>>>(
        (const uint4*)h, rowoff, csrsrc, agg2);
    fused_mlp<HID_C, OUT_C, false, false><<<mTiles, 512, SM2>>>(
        agg2, Wf3, b1b, Wf4, b2b, out);
}

// round 17
// speedup vs baseline: 1.5398x; 1.0307x over previous
#include <cuda_runtime.h>
#include <cuda_fp16.h>
#include <cstdint>

#define N_NODES 100000
#define N_EDGES 1600000
#define IN_C 128
#define HID_C 256
#define OUT_C 128
#define SCAN_NB ((N_NODES + 1023) / 1024)   // 98

// ================= scratch =================
__device__ __half  g_xh  [N_NODES * IN_C];       // fp16 copy of x
__device__ __half  g_agg1[N_NODES * IN_C];       // fp16 aggregated input (conv1)
__device__ __half  g_h   [N_NODES * HID_C];      // conv1 output (fp16, relu)
__device__ __half  g_agg2[N_NODES * HID_C];      // fp16 aggregated input (conv2)
__device__ __half  g_Wf1[IN_C * HID_C];          // fragment-packed fp16 weights
__device__ __half  g_Wf2[HID_C * HID_C];
__device__ __half  g_Wf3[HID_C * HID_C];
__device__ __half  g_Wf4[HID_C * OUT_C];
__device__ int     g_cnt[N_NODES];
__device__ int     g_rowoff[N_NODES + 1];
__device__ int     g_cursor[N_NODES];
__device__ int     g_csrsrc[N_EDGES];
__device__ int     g_bsum[SCAN_NB];

// ================= helpers =================
__device__ __forceinline__ uint32_t smem_u32(const void* p) {
    uint32_t a;
    asm("{ .reg .u64 t; cvta.to.shared.u64 t, %1; cvt.u32.u64 %0, t; }" : "=r"(a) : "l"(p));
    return a;
}
__device__ __forceinline__ void cp_async16(uint32_t dst, const void* src, bool pred) {
    int sz = pred ? 16 : 0;
    asm volatile("cp.async.ca.shared.global [%0], [%1], 16, %2;"
                 :: "r"(dst), "l"(src), "r"(sz) : "memory");
}
#define CP_COMMIT() asm volatile("cp.async.commit_group;" ::: "memory")
#define CP_WAIT(n)  asm volatile("cp.async.wait_group %0;" :: "n"(n) : "memory")

__device__ __forceinline__ void mma_f16(float* d, uint32_t a0, uint32_t a1,
                                        uint32_t a2, uint32_t a3,
                                        uint32_t b0, uint32_t b1) {
    asm volatile(
        "mma.sync.aligned.m16n8k16.row.col.f32.f16.f16.f32 "
        "{%0,%1,%2,%3}, {%4,%5,%6,%7}, {%8,%9}, {%0,%1,%2,%3};"
        : "+f"(d[0]), "+f"(d[1]), "+f"(d[2]), "+f"(d[3])
        : "r"(a0), "r"(a1), "r"(a2), "r"(a3), "r"(b0), "r"(b1));
}
__device__ __forceinline__ uint32_t pack_h2(float lo, float hi) {
    __half2 h = __floats2half2_rn(lo, hi);
    return *(uint32_t*)&h;
}
__device__ __forceinline__ void h8_add(float* acc, uint4 v) {
    float2 f;
    f = __half22float2(*(__half2*)&v.x); acc[0] += f.x; acc[1] += f.y;
    f = __half22float2(*(__half2*)&v.y); acc[2] += f.x; acc[3] += f.y;
    f = __half22float2(*(__half2*)&v.z); acc[4] += f.x; acc[5] += f.y;
    f = __half22float2(*(__half2*)&v.w); acc[6] += f.x; acc[7] += f.y;
}
__device__ __forceinline__ void h4_add(float* acc, uint2 v) {
    float2 f;
    f = __half22float2(*(__half2*)&v.x); acc[0] += f.x; acc[1] += f.y;
    f = __half22float2(*(__half2*)&v.y); acc[2] += f.x; acc[3] += f.y;
}

// ================= fused prep: zero cnt + convert x + pack 4 weights =================
// runtime-parameter fragment pack (same layout as before)
__device__ __forceinline__ void pack_dev(const float* __restrict__ W,
                                         __half* __restrict__ Wf,
                                         int NTOT, int id, int total)
{
    if (id >= total) return;
    int NT = NTOT / 64;
    int PER_G = 4 * NTOT;
    int q  = id % PER_G;
    int g  = id / PER_G;
    int lane = q & 31;
    int p    = (q >> 5) & 3;
    int rest = q >> 7;
    int wt   = rest % NT;
    int ks   = rest / NT;

    int gid = lane >> 2, tig = lane & 3;
    int n0 = wt * 64 + 2 * p * 8 + gid;
    int k0 = g * 32 + ks * 16 + tig * 2;

    uint4 v;
    v.x = pack_h2(W[(size_t)k0       * NTOT + n0],     W[(size_t)(k0 + 1) * NTOT + n0]);
    v.y = pack_h2(W[(size_t)(k0 + 8) * NTOT + n0],     W[(size_t)(k0 + 9) * NTOT + n0]);
    v.z = pack_h2(W[(size_t)k0       * NTOT + n0 + 8], W[(size_t)(k0 + 1) * NTOT + n0 + 8]);
    v.w = pack_h2(W[(size_t)(k0 + 8) * NTOT + n0 + 8], W[(size_t)(k0 + 9) * NTOT + n0 + 8]);
    *(uint4*)&Wf[(size_t)id * 8] = v;
}

// block ranges
#define ZB 391                               // zero cnt: 100000/256
#define CB 6250                              // convert: 1.6M uint4 / 256
#define P1B 16                               // pack W1a: 4096/256
#define P2B 32                               // pack W2a: 8192/256
#define P3B 32                               // pack W1b
#define P4B 16                               // pack W2b
#define PREP_BLOCKS (ZB + CB + P1B + P2B + P3B + P4B)   // 6737

__global__ void __launch_bounds__(256) prep_kernel(
    const float4* __restrict__ x, uint4* __restrict__ xh,
    const float* __restrict__ W1a, __half* __restrict__ Wf1,
    const float* __restrict__ W2a, __half* __restrict__ Wf2,
    const float* __restrict__ W1b, __half* __restrict__ Wf3,
    const float* __restrict__ W2b, __half* __restrict__ Wf4,
    int* __restrict__ cnt)
{
    int blk = blockIdx.x;
    if (blk < ZB) {
        int i = blk * 256 + threadIdx.x;
        if (i < N_NODES) cnt[i] = 0;
        return;
    }
    blk -= ZB;
    if (blk < CB) {
        int i = blk * 256 + threadIdx.x;    // always < 1.6M (6250*256 exactly)
        float4 a = x[2 * i], b = x[2 * i + 1];
        uint4 o;
        o.x = pack_h2(a.x, a.y);
        o.y = pack_h2(a.z, a.w);
        o.z = pack_h2(b.x, b.y);
        o.w = pack_h2(b.z, b.w);
        xh[i] = o;
        return;
    }
    blk -= CB;
    if (blk < P1B) { pack_dev(W1a, Wf1, HID_C, blk * 256 + threadIdx.x, IN_C  * HID_C / 8); return; }
    blk -= P1B;
    if (blk < P2B) { pack_dev(W2a, Wf2, HID_C, blk * 256 + threadIdx.x, HID_C * HID_C / 8); return; }
    blk -= P2B;
    if (blk < P3B) { pack_dev(W1b, Wf3, HID_C, blk * 256 + threadIdx.x, HID_C * HID_C / 8); return; }
    blk -= P3B;
    pack_dev(W2b, Wf4, OUT_C, blk * 256 + threadIdx.x, HID_C * OUT_C / 8);
}

// ================= CSR build =================
__global__ void hist_kernel(const int* __restrict__ dst, int* __restrict__ cnt)
{
    int e = blockIdx.x * 256 + threadIdx.x;
    if (e < N_EDGES) atomicAdd(&cnt[dst[e]], 1);
}

__global__ void scan1_kernel(const int* __restrict__ cnt, int* __restrict__ rowoff,
                             int* __restrict__ bsum)
{
    __shared__ int sh[1024];
    int tid = threadIdx.x;
    int i = blockIdx.x * 1024 + tid;
    int v = (i < N_NODES) ? cnt[i] : 0;
    sh[tid] = v;
    __syncthreads();
#pragma unroll
    for (int off = 1; off < 1024; off <<= 1) {
        int t = (tid >= off) ? sh[tid - off] : 0;
        __syncthreads();
        sh[tid] += t;
        __syncthreads();
    }
    if (i < N_NODES) rowoff[i] = sh[tid] - v;
    if (tid == 1023) bsum[blockIdx.x] = sh[tid];
}

// fused scan2+scan3: each block reduces bsum[0..blockIdx-1] itself
__global__ void scan3_kernel(int* __restrict__ rowoff, const int* __restrict__ bsum,
                             int* __restrict__ cursor)
{
    __shared__ int sh[128];
    int tid = threadIdx.x;
    if (tid < 128)
        sh[tid] = (tid < (int)blockIdx.x && tid < SCAN_NB) ? bsum[tid] : 0;
    __syncthreads();
    if (tid < 64) sh[tid] += sh[tid + 64];
    __syncthreads();
    if (tid < 32) {
        int v = sh[tid] + sh[tid + 32];
#pragma unroll
        for (int o = 16; o > 0; o >>= 1)
            v += __shfl_down_sync(0xFFFFFFFF, v, o);
        if (tid == 0) sh[0] = v;
    }
    __syncthreads();
    int off = sh[0];

    int i = blockIdx.x * 1024 + tid;
    if (i < N_NODES) {
        int r = rowoff[i] + off;
        rowoff[i] = r;
        cursor[i] = r;
    }
    if (i == 0) rowoff[N_NODES] = N_EDGES;
}

__global__ void fill_kernel(const int* __restrict__ src, const int* __restrict__ dst,
                            int* __restrict__ cursor, int* __restrict__ csrsrc)
{
    int e = blockIdx.x * 256 + threadIdx.x;
    if (e >= N_EDGES) return;
    int pos = atomicAdd(&cursor[dst[e]], 1);
    csrsrc[pos] = src[e];
}

// ================= CSR gather-reduce, fp16 source, 128ch =================
__global__ void __launch_bounds__(256, 6) csr_reduce_h16_128(
    const uint2* __restrict__ x,
    const int* __restrict__ rowoff,
    const int* __restrict__ csrsrc,
    __half* __restrict__ agg)
{
    int node = (int)((blockIdx.x * 256u + threadIdx.x) >> 5);
    if (node >= N_NODES) return;
    int lane = threadIdx.x & 31;

    float acc[4] = {0, 0, 0, 0};
    h4_add(acc, x[(size_t)node * 32 + lane]);

    int b = __ldg(&rowoff[node]);
    int e = __ldg(&rowoff[node + 1]);
    for (; b + 3 < e; b += 4) {
        int s0 = __ldg(&csrsrc[b]);
        int s1 = __ldg(&csrsrc[b + 1]);
        int s2 = __ldg(&csrsrc[b + 2]);
        int s3 = __ldg(&csrsrc[b + 3]);
        uint2 v0 = x[(size_t)s0 * 32 + lane];
        uint2 v1 = x[(size_t)s1 * 32 + lane];
        uint2 v2 = x[(size_t)s2 * 32 + lane];
        uint2 v3 = x[(size_t)s3 * 32 + lane];
        h4_add(acc, v0);
        h4_add(acc, v1);
        h4_add(acc, v2);
        h4_add(acc, v3);
    }
    for (; b < e; b++)
        h4_add(acc, x[(size_t)__ldg(&csrsrc[b]) * 32 + lane]);

    uint2 o;
    o.x = pack_h2(acc[0], acc[1]);
    o.y = pack_h2(acc[2], acc[3]);
    *(uint2*)&agg[(size_t)node * 128 + lane * 4] = o;
}

// ================= CSR gather-reduce, fp16 source, 256ch =================
__global__ void __launch_bounds__(256, 6) csr_reduce_h16_256(
    const uint4* __restrict__ x,
    const int* __restrict__ rowoff,
    const int* __restrict__ csrsrc,
    __half* __restrict__ agg)
{
    int node = (int)((blockIdx.x * 256u + threadIdx.x) >> 5);
    if (node >= N_NODES) return;
    int lane = threadIdx.x & 31;

    float acc[8] = {0, 0, 0, 0, 0, 0, 0, 0};
    h8_add(acc, x[(size_t)node * 32 + lane]);

    int b = __ldg(&rowoff[node]);
    int e = __ldg(&rowoff[node + 1]);
    for (; b + 3 < e; b += 4) {
        int s0 = __ldg(&csrsrc[b]);
        int s1 = __ldg(&csrsrc[b + 1]);
        int s2 = __ldg(&csrsrc[b + 2]);
        int s3 = __ldg(&csrsrc[b + 3]);
        uint4 v0 = x[(size_t)s0 * 32 + lane];
        uint4 v1 = x[(size_t)s1 * 32 + lane];
        uint4 v2 = x[(size_t)s2 * 32 + lane];
        uint4 v3 = x[(size_t)s3 * 32 + lane];
        h8_add(acc, v0);
        h8_add(acc, v1);
        h8_add(acc, v2);
        h8_add(acc, v3);
    }
    for (; b < e; b++)
        h8_add(acc, x[(size_t)__ldg(&csrsrc[b]) * 32 + lane]);

    uint4 o;
    o.x = pack_h2(acc[0], acc[1]);
    o.y = pack_h2(acc[2], acc[3]);
    o.z = pack_h2(acc[4], acc[5]);
    o.w = pack_h2(acc[6], acc[7]);
    *(uint4*)&agg[(size_t)node * 256 + lane * 8] = o;
}

// ================= fused 2-layer MLP, fp16 MMA =================
template <int K, int N2, bool OUTER_RELU, bool HALF_OUT>
__global__ void __launch_bounds__(512) fused_mlp(
    const __half* __restrict__ A,
    const __half* __restrict__ Wp1,
    const float* __restrict__ b1v,
    const __half* __restrict__ Wp2,
    const float* __restrict__ b2v,
    void* __restrict__ Cv)
{
    constexpr int BM = 128;
    constexpr int GA = K / 32, GB = HID_C / 32;
    constexpr int NT2 = N2 / 64;
    constexpr int NF  = N2 / 32;
    constexpr int NPL = NF / 2;
    constexpr int M = N_NODES;
    constexpr int AP = 40, HP = 264;
    constexpr int ABUF  = BM * AP;
    constexpr int W1OFF = 2 * ABUF;
    constexpr int WBUF1 = 8192;
    constexpr int W2OFF = BM * HP;
    constexpr int WBUF2 = 32 * N2;

    extern __shared__ __half smh[];
    const uint32_t sbase = smem_u32(smh);

    const int tid  = threadIdx.x;
    const int wid  = tid >> 5;
    const int lane = tid & 31;
    const int gid  = lane >> 2;
    const int tig  = lane & 3;
    const int wm   = wid & 3;
    const int wn   = wid >> 2;
    const int rA   = wm * 32;
    const int m0   = blockIdx.x * BM;

    float acc[2][8][4];
#pragma unroll
    for (int i = 0; i < 2; i++)
#pragma unroll
        for (int j = 0; j < 8; j++)
#pragma unroll
            for (int c = 0; c < 4; c++) acc[i][j][c] = 0.0f;

    auto loadA = [&](int g) {
        const int s = g & 1;
        {
            int row = tid >> 2, c4 = tid & 3;
            cp_async16(sbase + (uint32_t)(s * ABUF + row * AP + c4 * 8) * 2u,
                       A + (size_t)(m0 + row) * K + g * 32 + c4 * 8,
                       (m0 + row) < M);
        }
#pragma unroll
        for (int j = 0; j < 2; j++) {
            int idx = j * 512 + tid;
            cp_async16(sbase + (uint32_t)(W1OFF + s * WBUF1 + idx * 8) * 2u,
                       Wp1 + (size_t)g * WBUF1 + idx * 8, true);
        }
        CP_COMMIT();
    };
    auto loadB = [&](int g) {
        const int s = g & 1;
#pragma unroll
        for (int j = 0; j < WBUF2 / 8 / 512; j++) {
            int idx = j * 512 + tid;
            cp_async16(sbase + (uint32_t)(W2OFF + s * WBUF2 + idx * 8) * 2u,
                       Wp2 + (size_t)g * WBUF2 + idx * 8, true);
        }
        CP_COMMIT();
    };

    // ---- phase A: Hacc = A @ W1 ----
    loadA(0);
    for (int g = 0; g < GA; g++) {
        if (g + 1 < GA) { loadA(g + 1); CP_WAIT(1); }
        else            { CP_WAIT(0); }
        __syncthreads();
        const __half* ah = smh + (g & 1) * ABUF;
        const float4* bf = (const float4*)(smh + W1OFF + (g & 1) * WBUF1);
#pragma unroll
        for (int ks = 0; ks < 2; ks++) {
            const int k0 = ks * 16 + 2 * tig;
            uint32_t a[2][4];
#pragma unroll
            for (int mf = 0; mf < 2; mf++) {
                int base = rA + mf * 16;
                a[mf][0] = *(const uint32_t*)&smh[((g & 1) * ABUF) + (base + gid)     * AP + k0];
                a[mf][1] = *(const uint32_t*)&smh[((g & 1) * ABUF) + (base + gid + 8) * AP + k0];
                a[mf][2] = *(const uint32_t*)&smh[((g & 1) * ABUF) + (base + gid)     * AP + k0 + 8];
                a[mf][3] = *(const uint32_t*)&smh[((g & 1) * ABUF) + (base + gid + 8) * AP + k0 + 8];
            }
            (void)ah;
            uint32_t b[8][2];
#pragma unroll
            for (int p = 0; p < 4; p++) {
                float4 q = bf[((ks * 4 + wn) * 4 + p) * 32 + lane];
                b[2 * p][0]     = __float_as_uint(q.x);
                b[2 * p][1]     = __float_as_uint(q.y);
                b[2 * p + 1][0] = __float_as_uint(q.z);
                b[2 * p + 1][1] = __float_as_uint(q.w);
            }
#pragma unroll
            for (int mf = 0; mf < 2; mf++)
#pragma unroll
                for (int nf = 0; nf < 8; nf++)
                    mma_f16(acc[mf][nf], a[mf][0], a[mf][1], a[mf][2], a[mf][3],
                            b[nf][0], b[nf][1]);
        }
        __syncthreads();
    }

    loadB(0);

    // ---- spill H = fp16(relu(acc + b1)) into smem ----
#pragma unroll
    for (int nf = 0; nf < 8; nf++) {
        int col = wn * 64 + nf * 8 + tig * 2;
        float c0 = b1v[col], c1 = b1v[col + 1];
#pragma unroll
        for (int mf = 0; mf < 2; mf++) {
            int r0 = rA + mf * 16 + gid;
            *(uint32_t*)&smh[(size_t)r0 * HP + col] =
                pack_h2(fmaxf(acc[mf][nf][0] + c0, 0.f), fmaxf(acc[mf][nf][1] + c1, 0.f));
            *(uint32_t*)&smh[(size_t)(r0 + 8) * HP + col] =
                pack_h2(fmaxf(acc[mf][nf][2] + c0, 0.f), fmaxf(acc[mf][nf][3] + c1, 0.f));
        }
    }
#pragma unroll
    for (int i = 0; i < 2; i++)
#pragma unroll
        for (int j = 0; j < 8; j++)
#pragma unroll
            for (int c = 0; c < 4; c++) acc[i][j][c] = 0.0f;

    // ---- phase 4: OUT = H @ W2 ----
    const int grp = (NF == 8) ? wn : (wn >> 1);
    for (int g = 0; g < GB; g++) {
        if (g + 1 < GB) { loadB(g + 1); CP_WAIT(1); }
        else            { CP_WAIT(0); }
        __syncthreads();
        const float4* bf = (const float4*)(smh + W2OFF + (g & 1) * WBUF2);
#pragma unroll
        for (int ks = 0; ks < 2; ks++) {
            const int k0 = g * 32 + ks * 16 + 2 * tig;
            uint32_t a[2][4];
#pragma unroll
            for (int mf = 0; mf < 2; mf++) {
                int base = rA + mf * 16;
                a[mf][0] = *(const uint32_t*)&smh[(size_t)(base + gid)     * HP + k0];
                a[mf][1] = *(const uint32_t*)&smh[(size_t)(base + gid + 8) * HP + k0];
                a[mf][2] = *(const uint32_t*)&smh[(size_t)(base + gid)     * HP + k0 + 8];
                a[mf][3] = *(const uint32_t*)&smh[(size_t)(base + gid + 8) * HP + k0 + 8];
            }
            uint32_t b[8][2];
#pragma unroll
            for (int pl = 0; pl < NPL; pl++) {
                int p = (NF == 8) ? pl : (2 * (wn & 1) + pl);
                float4 q = bf[((ks * NT2 + grp) * 4 + p) * 32 + lane];
                b[2 * pl][0]     = __float_as_uint(q.x);
                b[2 * pl][1]     = __float_as_uint(q.y);
                b[2 * pl + 1][0] = __float_as_uint(q.z);
                b[2 * pl + 1][1] = __float_as_uint(q.w);
            }
#pragma unroll
            for (int mf = 0; mf < 2; mf++)
#pragma unroll
                for (int nf = 0; nf < NF; nf++)
                    mma_f16(acc[mf][nf], a[mf][0], a[mf][1], a[mf][2], a[mf][3],
                            b[nf][0], b[nf][1]);
        }
        __syncthreads();
    }

    // ---- epilogue ----
#pragma unroll
    for (int nf = 0; nf < NF; nf++) {
        int col = wn * (N2 / 4) + nf * 8 + tig * 2;
        float c0 = b2v[col], c1 = b2v[col + 1];
#pragma unroll
        for (int mf = 0; mf < 2; mf++) {
            int r0 = m0 + rA + mf * 16 + gid;
            float v0 = acc[mf][nf][0] + c0, v1 = acc[mf][nf][1] + c1;
            float v2 = acc[mf][nf][2] + c0, v3 = acc[mf][nf][3] + c1;
            if (OUTER_RELU) {
                v0 = fmaxf(v0, 0.f); v1 = fmaxf(v1, 0.f);
                v2 = fmaxf(v2, 0.f); v3 = fmaxf(v3, 0.f);
            }
            if (HALF_OUT) {
                __half* Ch = (__half*)Cv;
                if (r0 < M)
                    *(uint32_t*)&Ch[(size_t)r0 * N2 + col] = pack_h2(v0, v1);
                if (r0 + 8 < M)
                    *(uint32_t*)&Ch[(size_t)(r0 + 8) * N2 + col] = pack_h2(v2, v3);
            } else {
                float* Cf = (float*)Cv;
                if (r0 < M)
                    *(float2*)&Cf[(size_t)r0 * N2 + col] = make_float2(v0, v1);
                if (r0 + 8 < M)
                    *(float2*)&Cf[(size_t)(r0 + 8) * N2 + col] = make_float2(v2, v3);
            }
        }
    }
}

// ================= launch =================
extern "C" void kernel_launch(void* const* d_in, const int* in_sizes, int n_in,
                              void* d_out, int out_size)
{
    const float* x   = (const float*)d_in[0];
    const int*   ei  = (const int*)d_in[1];
    const float* W1a = (const float*)d_in[2];
    const float* b1a = (const float*)d_in[3];
    const float* W2a = (const float*)d_in[4];
    const float* b2a = (const float*)d_in[5];
    const float* W1b = (const float*)d_in[6];
    const float* b1b = (const float*)d_in[7];
    const float* W2b = (const float*)d_in[8];
    const float* b2b = (const float*)d_in[9];
    float* out = (float*)d_out;

    __half *xh, *agg1, *h, *agg2, *Wf1, *Wf2, *Wf3, *Wf4;
    int *cnt, *rowoff, *cursor, *csrsrc, *bsum;
    cudaGetSymbolAddress((void**)&xh,   g_xh);
    cudaGetSymbolAddress((void**)&agg1, g_agg1);
    cudaGetSymbolAddress((void**)&h,    g_h);
    cudaGetSymbolAddress((void**)&agg2, g_agg2);
    cudaGetSymbolAddress((void**)&Wf1,  g_Wf1);
    cudaGetSymbolAddress((void**)&Wf2,  g_Wf2);
    cudaGetSymbolAddress((void**)&Wf3,  g_Wf3);
    cudaGetSymbolAddress((void**)&Wf4,  g_Wf4);
    cudaGetSymbolAddress((void**)&cnt,    g_cnt);
    cudaGetSymbolAddress((void**)&rowoff, g_rowoff);
    cudaGetSymbolAddress((void**)&cursor, g_cursor);
    cudaGetSymbolAddress((void**)&csrsrc, g_csrsrc);
    cudaGetSymbolAddress((void**)&bsum,   g_bsum);

    const int* src = ei;
    const int* dst = ei + N_EDGES;

    const int mTiles = (N_NODES + 127) / 128;      // 782
    const int eBlocks = (N_EDGES + 255) / 256;
    const int nWarpBlocks = (N_NODES * 32 + 255) / 256;

    const int SM1 = (128 * 264 + 2 * 32 * HID_C) * 2;   // 100352 B
    const int SM2 = (128 * 264 + 2 * 32 * OUT_C) * 2;   //  83968 B
    cudaFuncSetAttribute(fused_mlp<IN_C,  HID_C, true,  true >,
                         cudaFuncAttributeMaxDynamicSharedMemorySize, SM1);
    cudaFuncSetAttribute(fused_mlp<HID_C, OUT_C, false, false>,
                         cudaFuncAttributeMaxDynamicSharedMemorySize, SM2);

    // ---- prep: zero cnt + x->fp16 + 4 weight packs (one launch) ----
    prep_kernel<<<PREP_BLOCKS, 256>>>(
        (const float4*)x, (uint4*)xh, W1a, Wf1, W2a, Wf2, W1b, Wf3, W2b, Wf4, cnt);

    // ---- CSR build: hist -> scan1 -> scan3(fused scan2) -> fill ----
    hist_kernel<<<eBlocks, 256>>>(dst, cnt);
    scan1_kernel<<<SCAN_NB, 1024>>>(cnt, rowoff, bsum);
    scan3_kernel<<<SCAN_NB, 1024>>>(rowoff, bsum, cursor);
    fill_kernel<<<eBlocks, 256>>>(src, dst, cursor, csrsrc);

    // ---- conv1: reduce + fused MLP (fp16 h out) ----
    csr_reduce_h16_128<<<nWarpBlocks, 256>>>(
        (const uint2*)xh, rowoff, csrsrc, agg1);
    fused_mlp<IN_C, HID_C, true, true><<<mTiles, 512, SM1>>>(
        agg1, Wf1, b1a, Wf2, b2a, h);

    // ---- conv2: reduce + fused MLP (fp32 out) ----
    csr_reduce_h16_256<<<nWarpBlocks, 256>>>(
        (const uint4*)h, rowoff, csrsrc, agg2);
    fused_mlp<HID_C, OUT_C, false, false><<<mTiles, 512, SM2>>>(
        agg2, Wf3, b1b, Wf4, b2b, out);
}